// round 16
// baseline (speedup 1.0000x reference)
#include <cuda_runtime.h>
#include <cuda_bf16.h>
#include <math.h>
#include <float.h>

#define N1    10000
#define EDG   160000
#define FIN   256
#define HID   500
#define K1SEL 5000
#define K2SEL 2500
#define NPAD  512

// ---------------- scratch (device globals; no allocation allowed) ----------------
__device__ float    g_agg1[(size_t)N1 * FIN];
__device__ float    g_h1[(size_t)N1 * HID];
__device__ float    g_score1[N1];    // raw dot h.p (pre-tanh), filled by gemm1 epilogue
__device__ float    g_score2[N1];    // raw dot for stage 2
__device__ int      g_selold[N1];
__device__ float    g_selval[N1];
__device__ int      g_newidx[N1];
__device__ int      g_mask[N1];
__device__ float    g_hp1[(size_t)K1SEL * HID];
__device__ float    g_agg2[(size_t)K1SEL * HID];
__device__ float    g_h2[(size_t)K1SEL * HID];
__device__ unsigned g_max1[HID];
__device__ float    g_sum1[HID];
__device__ unsigned g_max2[HID];
__device__ float    g_sum2[HID];
__device__ float    g_x1[2 * HID];
__device__ float    g_x2[2 * HID];
__device__ float    g_z[1000];
__device__ float    g_t1[2000];
__device__ float    g_t2[4000];
// compacted edges for conv2
__device__ int      g_ecnt;
__device__ int      g_cs[EDG];
__device__ int      g_cd[EDG];
__device__ float    g_cw[EDG];

// ---------------- init ----------------
__global__ void k_zero_init() {
    size_t i = (size_t)blockIdx.x * blockDim.x + threadIdx.x;
    size_t stride = (size_t)gridDim.x * blockDim.x;
    for (size_t j = i; j < (size_t)N1 * FIN; j += stride) {
        g_agg1[j] = 0.f;
        if (j < (size_t)K1SEL * HID) g_agg2[j] = 0.f;
        if (j < N1) { g_score1[j] = 0.f; g_score2[j] = 0.f; }
        if (j < HID) { g_max1[j] = 0u; g_sum1[j] = 0.f; g_max2[j] = 0u; g_sum2[j] = 0.f; }
        if (j == 0) g_ecnt = 0;
    }
}

// ---------------- vector reduction helper ----------------
__device__ __forceinline__ void red_add_v4(float* a, float x, float y, float z, float w) {
    asm volatile("red.global.add.v4.f32 [%0], {%1,%2,%3,%4};"
                 :: "l"(a), "f"(x), "f"(y), "f"(z), "f"(w) : "memory");
}

// ---------------- conv1 edge scatter: agg1[dst] += w * x[src] ----------------
__global__ void k_scatter1(const float* __restrict__ x, const int* __restrict__ src,
                           const int* __restrict__ dst, const float* __restrict__ ew) {
    long long t = (long long)blockIdx.x * blockDim.x + threadIdx.x;
    if (t >= (long long)EDG * 64) return;
    int e  = (int)(t >> 6);
    int c4 = (int)(t & 63);
    float w = ew[e];
    int s = src[e], d = dst[e];
    float4 v = ((const float4*)x)[(size_t)s * 64 + c4];
    float* a = &g_agg1[(size_t)d * FIN + c4 * 4];
    red_add_v4(a, w * v.x, w * v.y, w * v.z, w * v.w);
}

// ---------------- compact surviving edges after pool1 ----------------
__global__ void k_compact(const int* __restrict__ src, const int* __restrict__ dst,
                          const float* __restrict__ ew) {
    int e = blockIdx.x * blockDim.x + threadIdx.x;
    if (e >= EDG) return;
    int s = src[e], d = dst[e];
    if (g_mask[s] && g_mask[d]) {
        int p = atomicAdd(&g_ecnt, 1);
        g_cs[p] = g_newidx[s];
        g_cd[p] = g_newidx[d];
        g_cw[p] = ew[e];
    }
}

// ---------------- conv2 edge scatter (compacted) ----------------
__global__ void k_scatter2c() {
    long long t = (long long)blockIdx.x * blockDim.x + threadIdx.x;
    int e  = (int)(t / 125);
    if (e >= g_ecnt) return;
    int c4 = (int)(t % 125);
    float w = g_cw[e];
    int ns = g_cs[e], nd = g_cd[e];
    float4 v = ((const float4*)g_hp1)[(size_t)ns * 125 + c4];
    float* a = &g_agg2[(size_t)nd * HID + c4 * 4];
    red_add_v4(a, w * v.x, w * v.y, w * v.z, w * v.w);
}

// ---------------- fused fp32->bf16(hi/lo) dual NT GEMM on tensor cores ----------------
// C = relu(bias + A1@B1^T + A2@B2^T); also scoreraw[m] += sum_n C[m][n]*pw[n].
// Per k16 step: acc += hiA*hiB + loA*hiB + hiA*loB  (drops only lo*lo ~2^-18).
#define BM 64
#define BN 128
#define BKC 32
#define ASTR 40   // bf16 elems per smem row (80B) -> conflict-free ldmatrix

__device__ __forceinline__ unsigned su32(const void* p) {
    return (unsigned)__cvta_generic_to_shared(p);
}

__global__ void __launch_bounds__(256, 2) k_gemm_fused_relu(
    const float* __restrict__ A1, const float* __restrict__ B1,
    const float* __restrict__ A2, const float* __restrict__ B2,
    int Kreal, int Kpad,
    const float* __restrict__ bias, const float* __restrict__ pw,
    float* __restrict__ C, float* __restrict__ scoreraw,
    int M, int Nrows, int Nout) {
    __shared__ __align__(16) __nv_bfloat16 Ah[BM][ASTR];
    __shared__ __align__(16) __nv_bfloat16 Al[BM][ASTR];
    __shared__ __align__(16) __nv_bfloat16 Bh[BN][ASTR];
    __shared__ __align__(16) __nv_bfloat16 Bl[BN][ASTR];
    int tid = threadIdx.x, lane = tid & 31, wid = tid >> 5;
    int warp_m = wid & 1, warp_n = wid >> 1;   // 2 x 4 warps
    int mBase = blockIdx.y * BM, nBase = blockIdx.x * BN;

    float acc[2][4][4];
#pragma unroll
    for (int i = 0; i < 2; i++)
#pragma unroll
        for (int j = 0; j < 4; j++)
#pragma unroll
            for (int q = 0; q < 4; q++) acc[i][j][q] = 0.f;

    int ra  = tid >> 2;            // A: 0..63
    int ca0 = (tid & 3) << 3;      // A: 0,8,16,24 floats
    int rb  = tid >> 1;            // B: 0..127
    int cb0 = (tid & 1) << 4;      // B: 0 or 16 floats

    for (int pass = 0; pass < 2; pass++) {
        const float* A = pass ? A2 : A1;
        const float* B = pass ? B2 : B1;
        for (int k0 = 0; k0 < Kpad; k0 += BKC) {
            __syncthreads();
            // ---- stage A row ra, cols [k0+ca0, k0+ca0+8) ----
            {
                float v[8];
                int grow = mBase + ra;
                const float* arow = A + (size_t)grow * Kreal + k0 + ca0;
                if (grow < M && k0 + ca0 + 7 < Kreal) {
#pragma unroll
                    for (int q = 0; q < 2; q++) {
                        float4 f = *(const float4*)(arow + q * 4);
                        v[q * 4 + 0] = f.x; v[q * 4 + 1] = f.y; v[q * 4 + 2] = f.z; v[q * 4 + 3] = f.w;
                    }
                } else {
#pragma unroll
                    for (int q = 0; q < 8; q++)
                        v[q] = (grow < M && k0 + ca0 + q < Kreal) ? arow[q] : 0.f;
                }
                __nv_bfloat162 hi[4], lo[4];
#pragma unroll
                for (int q = 0; q < 4; q++) {
                    float a0 = v[2 * q], a1 = v[2 * q + 1];
                    __nv_bfloat16 h0 = __float2bfloat16(a0), h1 = __float2bfloat16(a1);
                    __nv_bfloat16 l0 = __float2bfloat16(a0 - __bfloat162float(h0));
                    __nv_bfloat16 l1 = __float2bfloat16(a1 - __bfloat162float(h1));
                    hi[q] = __nv_bfloat162(h0, h1);
                    lo[q] = __nv_bfloat162(l0, l1);
                }
                *(uint4*)(&Ah[ra][ca0]) = *(uint4*)(&hi[0]);
                *(uint4*)(&Al[ra][ca0]) = *(uint4*)(&lo[0]);
            }
            // ---- stage B row rb, cols [k0+cb0, k0+cb0+16) ----
            {
                float v[16];
                int grow = nBase + rb;
                const float* brow = B + (size_t)grow * Kreal + k0 + cb0;
                if (grow < Nrows && k0 + cb0 + 15 < Kreal) {
#pragma unroll
                    for (int q = 0; q < 4; q++) {
                        float4 f = *(const float4*)(brow + q * 4);
                        v[q * 4 + 0] = f.x; v[q * 4 + 1] = f.y; v[q * 4 + 2] = f.z; v[q * 4 + 3] = f.w;
                    }
                } else {
#pragma unroll
                    for (int q = 0; q < 16; q++)
                        v[q] = (grow < Nrows && k0 + cb0 + q < Kreal) ? brow[q] : 0.f;
                }
                __nv_bfloat162 hi[8], lo[8];
#pragma unroll
                for (int q = 0; q < 8; q++) {
                    float a0 = v[2 * q], a1 = v[2 * q + 1];
                    __nv_bfloat16 h0 = __float2bfloat16(a0), h1 = __float2bfloat16(a1);
                    __nv_bfloat16 l0 = __float2bfloat16(a0 - __bfloat162float(h0));
                    __nv_bfloat16 l1 = __float2bfloat16(a1 - __bfloat162float(h1));
                    hi[q] = __nv_bfloat162(h0, h1);
                    lo[q] = __nv_bfloat162(l0, l1);
                }
                *(uint4*)(&Bh[rb][cb0])     = *(uint4*)(&hi[0]);
                *(uint4*)(&Bh[rb][cb0 + 8]) = *(uint4*)(&hi[4]);
                *(uint4*)(&Bl[rb][cb0])     = *(uint4*)(&lo[0]);
                *(uint4*)(&Bl[rb][cb0 + 8]) = *(uint4*)(&lo[4]);
            }
            __syncthreads();
#pragma unroll
            for (int kk = 0; kk < BKC; kk += 16) {
                unsigned ah[2][4], al[2][4];
#pragma unroll
                for (int i = 0; i < 2; i++) {
                    int row = warp_m * 32 + i * 16 + (lane & 15);
                    int col = kk + ((lane >> 4) << 3);
                    unsigned addr = su32(&Ah[row][col]);
                    asm volatile("ldmatrix.sync.aligned.m8n8.x4.shared.b16 {%0,%1,%2,%3}, [%4];"
                                 : "=r"(ah[i][0]), "=r"(ah[i][1]), "=r"(ah[i][2]), "=r"(ah[i][3])
                                 : "r"(addr));
                    addr = su32(&Al[row][col]);
                    asm volatile("ldmatrix.sync.aligned.m8n8.x4.shared.b16 {%0,%1,%2,%3}, [%4];"
                                 : "=r"(al[i][0]), "=r"(al[i][1]), "=r"(al[i][2]), "=r"(al[i][3])
                                 : "r"(addr));
                }
#pragma unroll
                for (int j2 = 0; j2 < 2; j2++) {
                    unsigned bh[4], bl[4];
                    int row = warp_n * 32 + j2 * 16 + (lane & 7) + ((lane >> 4) << 3);
                    int col = kk + (((lane >> 3) & 1) << 3);
                    unsigned addr = su32(&Bh[row][col]);
                    asm volatile("ldmatrix.sync.aligned.m8n8.x4.shared.b16 {%0,%1,%2,%3}, [%4];"
                                 : "=r"(bh[0]), "=r"(bh[1]), "=r"(bh[2]), "=r"(bh[3])
                                 : "r"(addr));
                    addr = su32(&Bl[row][col]);
                    asm volatile("ldmatrix.sync.aligned.m8n8.x4.shared.b16 {%0,%1,%2,%3}, [%4];"
                                 : "=r"(bl[0]), "=r"(bl[1]), "=r"(bl[2]), "=r"(bl[3])
                                 : "r"(addr));
#pragma unroll
                    for (int i = 0; i < 2; i++) {
#pragma unroll
                        for (int jj = 0; jj < 2; jj++) {
                            int j = j2 * 2 + jj;
                            unsigned b0h = bh[jj ? 2 : 0], b1h = bh[jj ? 3 : 1];
                            unsigned b0l = bl[jj ? 2 : 0], b1l = bl[jj ? 3 : 1];
                            asm volatile(
                                "mma.sync.aligned.m16n8k16.row.col.f32.bf16.bf16.f32 "
                                "{%0,%1,%2,%3}, {%4,%5,%6,%7}, {%8,%9}, {%0,%1,%2,%3};"
                                : "+f"(acc[i][j][0]), "+f"(acc[i][j][1]),
                                  "+f"(acc[i][j][2]), "+f"(acc[i][j][3])
                                : "r"(ah[i][0]), "r"(ah[i][1]), "r"(ah[i][2]), "r"(ah[i][3]),
                                  "r"(b0h), "r"(b1h));
                            asm volatile(
                                "mma.sync.aligned.m16n8k16.row.col.f32.bf16.bf16.f32 "
                                "{%0,%1,%2,%3}, {%4,%5,%6,%7}, {%8,%9}, {%0,%1,%2,%3};"
                                : "+f"(acc[i][j][0]), "+f"(acc[i][j][1]),
                                  "+f"(acc[i][j][2]), "+f"(acc[i][j][3])
                                : "r"(al[i][0]), "r"(al[i][1]), "r"(al[i][2]), "r"(al[i][3]),
                                  "r"(b0h), "r"(b1h));
                            asm volatile(
                                "mma.sync.aligned.m16n8k16.row.col.f32.bf16.bf16.f32 "
                                "{%0,%1,%2,%3}, {%4,%5,%6,%7}, {%8,%9}, {%0,%1,%2,%3};"
                                : "+f"(acc[i][j][0]), "+f"(acc[i][j][1]),
                                  "+f"(acc[i][j][2]), "+f"(acc[i][j][3])
                                : "r"(ah[i][0]), "r"(ah[i][1]), "r"(ah[i][2]), "r"(ah[i][3]),
                                  "r"(b0l), "r"(b1l));
                        }
                    }
                }
            }
        }
    }
    // epilogue: bias + relu store, plus fused score partial dot
#pragma unroll
    for (int i = 0; i < 2; i++) {
        int m0 = mBase + warp_m * 32 + i * 16 + (lane >> 2);
        float rs0 = 0.f, rs1 = 0.f;    // row m0, row m0+8
#pragma unroll
        for (int j = 0; j < 4; j++) {
            int n0 = nBase + warp_n * 32 + j * 8 + ((lane & 3) << 1);
            if (n0 < Nout) {
                float bb = bias[n0], pv = pw[n0];
                float v0 = fmaxf(acc[i][j][0] + bb, 0.f);
                float v2 = fmaxf(acc[i][j][2] + bb, 0.f);
                if (m0 < M)     C[(size_t)m0 * Nout + n0]       = v0;
                if (m0 + 8 < M) C[(size_t)(m0 + 8) * Nout + n0] = v2;
                rs0 += v0 * pv; rs1 += v2 * pv;
            }
            if (n0 + 1 < Nout) {
                float bb = bias[n0 + 1], pv = pw[n0 + 1];
                float v1 = fmaxf(acc[i][j][1] + bb, 0.f);
                float v3 = fmaxf(acc[i][j][3] + bb, 0.f);
                if (m0 < M)     C[(size_t)m0 * Nout + n0 + 1]       = v1;
                if (m0 + 8 < M) C[(size_t)(m0 + 8) * Nout + n0 + 1] = v3;
                rs0 += v1 * pv; rs1 += v3 * pv;
            }
        }
        rs0 += __shfl_xor_sync(0xFFFFFFFFu, rs0, 1);
        rs0 += __shfl_xor_sync(0xFFFFFFFFu, rs0, 2);
        rs1 += __shfl_xor_sync(0xFFFFFFFFu, rs1, 1);
        rs1 += __shfl_xor_sync(0xFFFFFFFFu, rs1, 2);
        if ((lane & 3) == 0) {
            if (m0 < M)     atomicAdd(&scoreraw[m0], rs0);
            if (m0 + 8 < M) atomicAdd(&scoreraw[m0 + 8], rs1);
        }
    }
}

// ---------------- deterministic top-k selection (single block) ----------------
// Takes RAW dots; applies tanh(raw * rsqrt(sum p^2)). tanh saturates -> heavy
// key ties; histogram uses match_any aggregation with a UNIFORM trip count
// (bounds folded into the predicate, never diverging around ballot/match).
__device__ __forceinline__ int warpInclScan(int v) {
    int lane = threadIdx.x & 31;
#pragma unroll
    for (int o = 1; o < 32; o <<= 1) {
        int t = __shfl_up_sync(0xFFFFFFFFu, v, o);
        if (lane >= o) v += t;
    }
    return v;
}

__device__ __forceinline__ float key_to_val(unsigned u) {
    unsigned b = (u & 0x80000000u) ? (u ^ 0x80000000u) : ~u;
    return __uint_as_float(b);
}

__global__ void __launch_bounds__(1024) k_select_topk(
    const float* __restrict__ rawscore, const float* __restrict__ pw,
    int n, int k,
    int* __restrict__ sel_old, float* __restrict__ sel_val,
    int* __restrict__ new_idx, int* __restrict__ mask) {
    __shared__ unsigned skey[10016];
    __shared__ int hist[256];
    __shared__ int wsum[32];
    __shared__ int gtot[8];
    __shared__ unsigned sh_prefix;
    __shared__ int sh_rem;
    __shared__ float s_red[32];
    __shared__ float s_inv_sh;
    int tid = threadIdx.x;
    int lane = tid & 31, wid = tid >> 5;
    int iters = (n + 1023) >> 10;   // uniform trip count for all threads

    // ---- s_inv = rsqrt(sum p^2) ----
    {
        float s = 0.f;
        for (int i = tid; i < HID; i += 1024) s += pw[i] * pw[i];
        for (int o = 16; o; o >>= 1) s += __shfl_down_sync(0xFFFFFFFFu, s, o);
        if (lane == 0) s_red[wid] = s;
        __syncthreads();
        if (tid == 0) {
            float t = 0.f;
            for (int i = 0; i < 32; i++) t += s_red[i];
            s_inv_sh = rsqrtf(t);
        }
        __syncthreads();
    }
    float s_inv = s_inv_sh;

    for (int i = tid; i < n; i += 1024) {
        float v = tanhf(rawscore[i] * s_inv);
        unsigned b = __float_as_uint(v);
        skey[i] = (b & 0x80000000u) ? ~b : (b | 0x80000000u);
    }
    if (tid == 0) { sh_prefix = 0u; sh_rem = k; }
    __syncthreads();

    // MSB-first radix select: find exact key T of the k-th largest score
    for (int shift = 24; shift >= 0; shift -= 8) {
        if (tid < 256) hist[tid] = 0;
        __syncthreads();
        unsigned premask = (shift == 24) ? 0u : (0xFFFFFFFFu << (shift + 8));
        unsigned pre = sh_prefix;
        int rem = sh_rem;
        // ballot-aggregated histogram; UNIFORM loop (no lane exits early)
        for (int it = 0; it < iters; it++) {
            int i = tid + (it << 10);
            bool inb = (i < n);
            unsigned u = inb ? skey[i] : 0u;
            bool p = inb && ((u & premask) == pre);
            unsigned act = __ballot_sync(0xFFFFFFFFu, p);
            if (p) {
                unsigned bin = (u >> shift) & 255u;
                unsigned peers = __match_any_sync(act, bin);
                int leader = __ffs((int)peers) - 1;
                if (lane == leader) atomicAdd(&hist[bin], __popc(peers));
            }
        }
        __syncthreads();
        // parallel suffix-sum bin pick: the b with suffix_excl(b) < rem <= suffix_excl(b)+hist[b]
        {
            bool valid = (tid < 256);
            int v = valid ? hist[tid] : 0;
            int sv = v;  // inclusive suffix within 32-bin group
#pragma unroll
            for (int o = 1; o < 32; o <<= 1) {
                int t = __shfl_down_sync(0xFFFFFFFFu, sv, o);
                if (lane + o < 32) sv += t;
            }
            if (valid && lane == 0) gtot[tid >> 5] = sv;
            __syncthreads();
            if (tid == 0) {
                int acc = 0;
                for (int g = 7; g >= 0; g--) { int t = gtot[g]; gtot[g] = acc; acc += t; }
            }
            __syncthreads();
            if (valid) {
                int suf_excl = (sv - v) + gtot[tid >> 5];  // count of keys in bins > tid
                if (suf_excl < rem && suf_excl + v >= rem) {
                    sh_prefix = pre | ((unsigned)tid << shift);
                    sh_rem = rem - suf_excl;
                }
            }
        }
        __syncthreads();
    }
    unsigned T = sh_prefix;
    int r = sh_rem;  // number of ==T entries to keep (lowest index first, matching lax.top_k)

    int ch = (n + 1023) / 1024;
    int beg = tid * ch; if (beg > n) beg = n;
    int end = beg + ch; if (end > n) end = n;

    int eqc = 0;
    for (int i = beg; i < end; i++) eqc += (skey[i] == T);
    int inc = warpInclScan(eqc);
    if (lane == 31) wsum[wid] = inc;
    __syncthreads();
    if (wid == 0) { int v = wsum[lane]; int wi = warpInclScan(v); wsum[lane] = wi - v; }
    __syncthreads();
    int eqbase = wsum[wid] + inc - eqc;
    __syncthreads();

    int selc = 0;
    {
        int er = eqbase;
        for (int i = beg; i < end; i++) {
            unsigned u = skey[i];
            bool eq = (u == T);
            bool sel = (u > T) || (eq && er < r);
            if (eq) er++;
            selc += sel;
        }
    }
    int inc2 = warpInclScan(selc);
    if (lane == 31) wsum[wid] = inc2;
    __syncthreads();
    if (wid == 0) { int v = wsum[lane]; int wi = warpInclScan(v); wsum[lane] = wi - v; }
    __syncthreads();
    int selbase = wsum[wid] + inc2 - selc;

    {
        int er = eqbase, pos = selbase;
        for (int i = beg; i < end; i++) {
            unsigned u = skey[i];
            bool eq = (u == T);
            bool sel = (u > T) || (eq && er < r);
            if (eq) er++;
            if (sel) {
                sel_old[pos] = i;
                sel_val[pos] = key_to_val(u);
                new_idx[i] = pos;
                mask[i] = 1;
                pos++;
            } else {
                new_idx[i] = 0;
                mask[i] = 0;
            }
        }
    }
}

// ---------------- gather pooled features + fused max/sum readout ----------------
__global__ void k_gather_pool(const float* __restrict__ h, int kcnt,
                              const int* __restrict__ sel_old, const float* __restrict__ sel_val,
                              float* __restrict__ hp, unsigned* __restrict__ maxb,
                              float* __restrict__ sumb) {
    int c = blockIdx.x * blockDim.x + threadIdx.x;
    if (c >= HID) return;
    int rpb = (kcnt + gridDim.y - 1) / gridDim.y;
    int r0 = blockIdx.y * rpb;
    int r1 = r0 + rpb; if (r1 > kcnt) r1 = kcnt;
    unsigned mk = 0u;
    float sm = 0.f;
    for (int p = r0; p < r1; p++) {
        int old = sel_old[p];
        float v = h[(size_t)old * HID + c] * sel_val[p];
        if (hp) hp[(size_t)p * HID + c] = v;
        unsigned b = __float_as_uint(v);
        unsigned kk = (b & 0x80000000u) ? ~b : (b | 0x80000000u);
        if (kk > mk) mk = kk;
        sm += v;
    }
    if (r1 > r0) { atomicMax(&maxb[c], mk); atomicAdd(&sumb[c], sm); }
}

__global__ void k_finalize_readout(const unsigned* __restrict__ maxb,
                                   const float* __restrict__ sumb,
                                   float* __restrict__ xo, float invk) {
    int c = blockIdx.x * blockDim.x + threadIdx.x;
    if (c < HID) {
        unsigned u = maxb[c];
        unsigned b = (u & 0x80000000u) ? (u ^ 0x80000000u) : ~u;
        xo[c] = __uint_as_float(b);
        xo[HID + c] = sumb[c] * invk;
    }
}

__global__ void k_add_z() {
    int i = blockIdx.x * blockDim.x + threadIdx.x;
    if (i < 1000) g_z[i] = g_x1[i] + g_x2[i];
}

// ---------------- GEMV: y = act(W @ x + b), warp per row ----------------
__global__ void k_gemv_act(const float* __restrict__ W, const float* __restrict__ b,
                           const float* __restrict__ x, float* __restrict__ y,
                           int R, int K, int act) {
    int w = (blockIdx.x * blockDim.x + threadIdx.x) >> 5;
    int lane = threadIdx.x & 31;
    if (w >= R) return;
    const float4* W4 = (const float4*)(W + (size_t)w * K);
    const float4* X4 = (const float4*)x;
    int K4 = K >> 2;
    float s = 0.f;
    for (int i = lane; i < K4; i += 32) {
        float4 a = W4[i], c = X4[i];
        s += a.x * c.x + a.y * c.y + a.z * c.z + a.w * c.w;
    }
    for (int o = 16; o; o >>= 1) s += __shfl_down_sync(0xFFFFFFFFu, s, o);
    if (lane == 0) {
        s += b[w];
        y[w] = (act == 0) ? fmaxf(s, 0.f) : 1.f / (1.f + expf(-s));
    }
}

// ---------------- launch ----------------
extern "C" void kernel_launch(void* const* d_in, const int* in_sizes, int n_in,
                              void* d_out, int out_size) {
    const float* x       = (const float*)d_in[0];
    const int*   esrc    = (const int*)d_in[1];
    const int*   edst    = (const int*)d_in[2];
    const float* ew      = (const float*)d_in[3];
    const float* W1_rel  = (const float*)d_in[4];
    const float* b1      = (const float*)d_in[5];
    const float* W1_root = (const float*)d_in[6];
    const float* p1      = (const float*)d_in[7];
    const float* W2_rel  = (const float*)d_in[8];
    const float* b2      = (const float*)d_in[9];
    const float* W2_root = (const float*)d_in[10];
    const float* p2      = (const float*)d_in[11];
    const float* l1W     = (const float*)d_in[12];
    const float* l1b     = (const float*)d_in[13];
    const float* l2W     = (const float*)d_in[14];
    const float* l2b     = (const float*)d_in[15];
    const float* l3W     = (const float*)d_in[16];
    const float* l3b     = (const float*)d_in[17];
    float* out = (float*)d_out;

    float *p_agg1, *p_h1, *p_hp1, *p_agg2, *p_h2, *p_sc1, *p_sc2, *p_selval;
    float *p_x1, *p_x2, *p_z, *p_t1, *p_t2, *p_sum1, *p_sum2;
    int *p_selold, *p_newidx, *p_mask;
    unsigned *p_max1, *p_max2;
    cudaGetSymbolAddress((void**)&p_agg1, g_agg1);
    cudaGetSymbolAddress((void**)&p_h1, g_h1);
    cudaGetSymbolAddress((void**)&p_hp1, g_hp1);
    cudaGetSymbolAddress((void**)&p_agg2, g_agg2);
    cudaGetSymbolAddress((void**)&p_h2, g_h2);
    cudaGetSymbolAddress((void**)&p_sc1, g_score1);
    cudaGetSymbolAddress((void**)&p_sc2, g_score2);
    cudaGetSymbolAddress((void**)&p_selval, g_selval);
    cudaGetSymbolAddress((void**)&p_selold, g_selold);
    cudaGetSymbolAddress((void**)&p_newidx, g_newidx);
    cudaGetSymbolAddress((void**)&p_mask, g_mask);
    cudaGetSymbolAddress((void**)&p_max1, g_max1);
    cudaGetSymbolAddress((void**)&p_sum1, g_sum1);
    cudaGetSymbolAddress((void**)&p_max2, g_max2);
    cudaGetSymbolAddress((void**)&p_sum2, g_sum2);
    cudaGetSymbolAddress((void**)&p_x1, g_x1);
    cudaGetSymbolAddress((void**)&p_x2, g_x2);
    cudaGetSymbolAddress((void**)&p_z, g_z);
    cudaGetSymbolAddress((void**)&p_t1, g_t1);
    cudaGetSymbolAddress((void**)&p_t2, g_t2);

    k_zero_init<<<4096, 256>>>();

    // ---- conv1 (+score1 fused) ----
    k_scatter1<<<(int)(((long long)EDG * 64 + 255) / 256), 256>>>(x, esrc, edst, ew);
    {
        dim3 g(NPAD / BN, (N1 + BM - 1) / BM);
        k_gemm_fused_relu<<<g, 256>>>(p_agg1, W1_rel, x, W1_root, FIN, FIN,
                                      b1, p1, p_h1, p_sc1, N1, HID, HID);
    }

    // ---- pool1 + readout1 ----
    k_select_topk<<<1, 1024>>>(p_sc1, p1, N1, K1SEL, p_selold, p_selval, p_newidx, p_mask);
    {
        dim3 g(4, 32);
        k_gather_pool<<<g, 128>>>(p_h1, K1SEL, p_selold, p_selval, p_hp1, p_max1, p_sum1);
    }
    k_finalize_readout<<<4, 128>>>(p_max1, p_sum1, p_x1, 1.f / (float)K1SEL);

    // ---- conv2 (+score2 fused) ----
    k_compact<<<(EDG + 255) / 256, 256>>>(esrc, edst, ew);
    k_scatter2c<<<(int)(((long long)EDG * 125 + 511) / 512), 512>>>();
    {
        dim3 g(NPAD / BN, (K1SEL + BM - 1) / BM);
        k_gemm_fused_relu<<<g, 256>>>(p_agg2, W2_rel, p_hp1, W2_root, HID, 512,
                                      b2, p2, p_h2, p_sc2, K1SEL, HID, HID);
    }

    // ---- pool2 + readout2 ----
    k_select_topk<<<1, 1024>>>(p_sc2, p2, K1SEL, K2SEL, p_selold, p_selval, p_newidx, p_mask);
    {
        dim3 g(4, 32);
        k_gather_pool<<<g, 128>>>(p_h2, K2SEL, p_selold, p_selval, nullptr, p_max2, p_sum2);
    }
    k_finalize_readout<<<4, 128>>>(p_max2, p_sum2, p_x2, 1.f / (float)K2SEL);

    // ---- MLP head ----
    k_add_z<<<1, 1024>>>();
    k_gemv_act<<<(2000 + 7) / 8, 256>>>(l1W, l1b, p_z, p_t1, 2000, 1000, 0);
    k_gemv_act<<<(4000 + 7) / 8, 256>>>(l2W, l2b, p_t1, p_t2, 4000, 2000, 0);
    k_gemv_act<<<(100 + 7) / 8, 256>>>(l3W, l3b, p_t2, out, 100, 4000, 1);
}

// round 17
// speedup vs baseline: 1.0980x; 1.0980x over previous
#include <cuda_runtime.h>
#include <cuda_bf16.h>
#include <math.h>
#include <float.h>

#define N1    10000
#define EDG   160000
#define FIN   256
#define HID   500
#define K1SEL 5000
#define K2SEL 2500
#define NPAD  512

// ---------------- scratch (device globals; no allocation allowed) ----------------
__device__ float    g_agg1[(size_t)N1 * FIN];
__device__ float    g_h1[(size_t)N1 * HID];
__device__ float    g_score1[N1];
__device__ float    g_score2[N1];
__device__ int      g_selold[N1];
__device__ float    g_selval[N1];
__device__ int      g_newidx[N1];
__device__ int      g_mask[N1];
__device__ float    g_hp1[(size_t)K1SEL * HID];
__device__ float    g_agg2[(size_t)K1SEL * HID];
__device__ float    g_h2[(size_t)K1SEL * HID];
__device__ unsigned g_max1[HID];
__device__ float    g_sum1[HID];
__device__ unsigned g_max2[HID];
__device__ float    g_sum2[HID];
__device__ float    g_x1[2 * HID];
__device__ float    g_x2[2 * HID];
__device__ float    g_z[1000];
__device__ float    g_t1[2000];
__device__ float    g_t2[4000];
__device__ int      g_ecnt;
__device__ int      g_cs[EDG];
__device__ int      g_cd[EDG];
__device__ float    g_cw[EDG];

// ---------------- init ----------------
__global__ void k_zero_init() {
    size_t i = (size_t)blockIdx.x * blockDim.x + threadIdx.x;
    size_t stride = (size_t)gridDim.x * blockDim.x;
    for (size_t j = i; j < (size_t)N1 * FIN; j += stride) {
        g_agg1[j] = 0.f;
        if (j < (size_t)K1SEL * HID) g_agg2[j] = 0.f;
        if (j < N1) { g_score1[j] = 0.f; g_score2[j] = 0.f; }
        if (j < HID) { g_max1[j] = 0u; g_sum1[j] = 0.f; g_max2[j] = 0u; g_sum2[j] = 0.f; }
        if (j == 0) g_ecnt = 0;
    }
}

// ---------------- vector reduction helper ----------------
__device__ __forceinline__ void red_add_v4(float* a, float x, float y, float z, float w) {
    asm volatile("red.global.add.v4.f32 [%0], {%1,%2,%3,%4};"
                 :: "l"(a), "f"(x), "f"(y), "f"(z), "f"(w) : "memory");
}

// ---------------- conv1 edge scatter: agg1[dst] += w * x[src] ----------------
__global__ void k_scatter1(const float* __restrict__ x, const int* __restrict__ src,
                           const int* __restrict__ dst, const float* __restrict__ ew) {
    long long t = (long long)blockIdx.x * blockDim.x + threadIdx.x;
    if (t >= (long long)EDG * 64) return;
    int e  = (int)(t >> 6);
    int c4 = (int)(t & 63);
    float w = ew[e];
    int s = src[e], d = dst[e];
    float4 v = ((const float4*)x)[(size_t)s * 64 + c4];
    float* a = &g_agg1[(size_t)d * FIN + c4 * 4];
    red_add_v4(a, w * v.x, w * v.y, w * v.z, w * v.w);
}

// ---------------- compact surviving edges after pool1 ----------------
__global__ void k_compact(const int* __restrict__ src, const int* __restrict__ dst,
                          const float* __restrict__ ew) {
    int e = blockIdx.x * blockDim.x + threadIdx.x;
    if (e >= EDG) return;
    int s = src[e], d = dst[e];
    if (g_mask[s] && g_mask[d]) {
        int p = atomicAdd(&g_ecnt, 1);
        g_cs[p] = g_newidx[s];
        g_cd[p] = g_newidx[d];
        g_cw[p] = ew[e];
    }
}

// ---------------- conv2 edge scatter (compacted) ----------------
__global__ void k_scatter2c() {
    long long t = (long long)blockIdx.x * blockDim.x + threadIdx.x;
    int e  = (int)(t / 125);
    if (e >= g_ecnt) return;
    int c4 = (int)(t % 125);
    float w = g_cw[e];
    int ns = g_cs[e], nd = g_cd[e];
    float4 v = ((const float4*)g_hp1)[(size_t)ns * 125 + c4];
    float* a = &g_agg2[(size_t)nd * HID + c4 * 4];
    red_add_v4(a, w * v.x, w * v.y, w * v.z, w * v.w);
}

// ---------------- fused fp32->bf16(hi/lo) dual NT GEMM, double-buffered ----------------
// C = relu(bias + A1@B1^T + A2@B2^T); also scoreraw[m] += sum_n C[m][n]*pw[n].
// Per k16 step: acc += hiA*hiB + loA*hiB + hiA*loB  (drops only lo*lo ~2^-18).
// Pipeline: LDG(chunk c+1) issued before MMA(chunk c); convert+STS to alt buffer
// overlaps MMA; ONE __syncthreads per chunk.
#define BM 64
#define BN 128
#define BKC 32
#define ASTR 40   // bf16 elems per smem row (80B) -> conflict-free ldmatrix
// per-buffer element counts (bf16)
#define AH_ELEMS (BM * ASTR)          // 2560
#define BH_ELEMS (BN * ASTR)          // 5120
#define BUF_ELEMS (2 * AH_ELEMS + 2 * BH_ELEMS)   // 15360 elems = 30720 B
#define SMEM_BYTES (2 * BUF_ELEMS * 2)            // 61440 B

__device__ __forceinline__ unsigned su32(const void* p) {
    return (unsigned)__cvta_generic_to_shared(p);
}

__global__ void __launch_bounds__(256, 2) k_gemm_fused_relu(
    const float* __restrict__ A1, const float* __restrict__ B1,
    const float* __restrict__ A2, const float* __restrict__ B2,
    int Kreal, int Kpad,
    const float* __restrict__ bias, const float* __restrict__ pw,
    float* __restrict__ C, float* __restrict__ scoreraw,
    int M, int Nrows, int Nout) {
    extern __shared__ __align__(16) __nv_bfloat16 sm[];
    int tid = threadIdx.x, lane = tid & 31, wid = tid >> 5;
    int warp_m = wid & 1, warp_n = wid >> 1;   // 2 x 4 warps
    int mBase = blockIdx.y * BM, nBase = blockIdx.x * BN;

    float acc[2][4][4];
#pragma unroll
    for (int i = 0; i < 2; i++)
#pragma unroll
        for (int j = 0; j < 4; j++)
#pragma unroll
            for (int q = 0; q < 4; q++) acc[i][j][q] = 0.f;

    int ra  = tid >> 2;            // A: 0..63
    int ca0 = (tid & 3) << 3;      // A: 0,8,16,24 floats
    int rb  = tid >> 1;            // B: 0..127
    int cb0 = (tid & 1) << 4;      // B: 0 or 16 floats

    int nch = Kpad / BKC;
    int total = 2 * nch;

    float va[8], vb[16];

    // ---- load chunk c's fp32 fragments into registers ----
    auto ldg_chunk = [&](int c) {
        int pass = (c >= nch) ? 1 : 0;
        int k0 = (c - pass * nch) * BKC;
        const float* A = pass ? A2 : A1;
        const float* B = pass ? B2 : B1;
        {
            int grow = mBase + ra;
            const float* arow = A + (size_t)grow * Kreal + k0 + ca0;
            if (grow < M && k0 + ca0 + 7 < Kreal) {
#pragma unroll
                for (int q = 0; q < 2; q++) {
                    float4 f = *(const float4*)(arow + q * 4);
                    va[q * 4 + 0] = f.x; va[q * 4 + 1] = f.y; va[q * 4 + 2] = f.z; va[q * 4 + 3] = f.w;
                }
            } else {
#pragma unroll
                for (int q = 0; q < 8; q++)
                    va[q] = (grow < M && k0 + ca0 + q < Kreal) ? arow[q] : 0.f;
            }
        }
        {
            int grow = nBase + rb;
            const float* brow = B + (size_t)grow * Kreal + k0 + cb0;
            if (grow < Nrows && k0 + cb0 + 15 < Kreal) {
#pragma unroll
                for (int q = 0; q < 4; q++) {
                    float4 f = *(const float4*)(brow + q * 4);
                    vb[q * 4 + 0] = f.x; vb[q * 4 + 1] = f.y; vb[q * 4 + 2] = f.z; vb[q * 4 + 3] = f.w;
                }
            } else {
#pragma unroll
                for (int q = 0; q < 16; q++)
                    vb[q] = (grow < Nrows && k0 + cb0 + q < Kreal) ? brow[q] : 0.f;
            }
        }
    };

    // ---- convert registers and store into buffer b ----
    auto stage_chunk = [&](int b) {
        __nv_bfloat16* Ah = sm + b * BUF_ELEMS;
        __nv_bfloat16* Al = Ah + AH_ELEMS;
        __nv_bfloat16* Bh = Al + AH_ELEMS;
        __nv_bfloat16* Bl = Bh + BH_ELEMS;
        {
            __nv_bfloat162 hi[4], lo[4];
#pragma unroll
            for (int q = 0; q < 4; q++) {
                float a0 = va[2 * q], a1 = va[2 * q + 1];
                __nv_bfloat16 h0 = __float2bfloat16(a0), h1 = __float2bfloat16(a1);
                __nv_bfloat16 l0 = __float2bfloat16(a0 - __bfloat162float(h0));
                __nv_bfloat16 l1 = __float2bfloat16(a1 - __bfloat162float(h1));
                hi[q] = __nv_bfloat162(h0, h1);
                lo[q] = __nv_bfloat162(l0, l1);
            }
            *(uint4*)(&Ah[ra * ASTR + ca0]) = *(uint4*)(&hi[0]);
            *(uint4*)(&Al[ra * ASTR + ca0]) = *(uint4*)(&lo[0]);
        }
        {
            __nv_bfloat162 hi[8], lo[8];
#pragma unroll
            for (int q = 0; q < 8; q++) {
                float a0 = vb[2 * q], a1 = vb[2 * q + 1];
                __nv_bfloat16 h0 = __float2bfloat16(a0), h1 = __float2bfloat16(a1);
                __nv_bfloat16 l0 = __float2bfloat16(a0 - __bfloat162float(h0));
                __nv_bfloat16 l1 = __float2bfloat16(a1 - __bfloat162float(h1));
                hi[q] = __nv_bfloat162(h0, h1);
                lo[q] = __nv_bfloat162(l0, l1);
            }
            *(uint4*)(&Bh[rb * ASTR + cb0])     = *(uint4*)(&hi[0]);
            *(uint4*)(&Bh[rb * ASTR + cb0 + 8]) = *(uint4*)(&hi[4]);
            *(uint4*)(&Bl[rb * ASTR + cb0])     = *(uint4*)(&lo[0]);
            *(uint4*)(&Bl[rb * ASTR + cb0 + 8]) = *(uint4*)(&lo[4]);
        }
    };

    // ---- prologue: stage chunk 0 into buffer 0 ----
    ldg_chunk(0);
    stage_chunk(0);
    __syncthreads();

    int cur = 0;
    for (int c = 0; c < total; c++) {
        bool more = (c + 1 < total);
        if (more) ldg_chunk(c + 1);   // LDG latency hidden under MMA below

        __nv_bfloat16* Ah = sm + cur * BUF_ELEMS;
        __nv_bfloat16* Al = Ah + AH_ELEMS;
        __nv_bfloat16* Bh = Al + AH_ELEMS;
        __nv_bfloat16* Bl = Bh + BH_ELEMS;

#pragma unroll
        for (int kk = 0; kk < BKC; kk += 16) {
            unsigned ah[2][4], al[2][4];
#pragma unroll
            for (int i = 0; i < 2; i++) {
                int row = warp_m * 32 + i * 16 + (lane & 15);
                int col = kk + ((lane >> 4) << 3);
                unsigned addr = su32(&Ah[row * ASTR + col]);
                asm volatile("ldmatrix.sync.aligned.m8n8.x4.shared.b16 {%0,%1,%2,%3}, [%4];"
                             : "=r"(ah[i][0]), "=r"(ah[i][1]), "=r"(ah[i][2]), "=r"(ah[i][3])
                             : "r"(addr));
                addr = su32(&Al[row * ASTR + col]);
                asm volatile("ldmatrix.sync.aligned.m8n8.x4.shared.b16 {%0,%1,%2,%3}, [%4];"
                             : "=r"(al[i][0]), "=r"(al[i][1]), "=r"(al[i][2]), "=r"(al[i][3])
                             : "r"(addr));
            }
#pragma unroll
            for (int j2 = 0; j2 < 2; j2++) {
                unsigned bh[4], bl[4];
                int row = warp_n * 32 + j2 * 16 + (lane & 7) + ((lane >> 4) << 3);
                int col = kk + (((lane >> 3) & 1) << 3);
                unsigned addr = su32(&Bh[row * ASTR + col]);
                asm volatile("ldmatrix.sync.aligned.m8n8.x4.shared.b16 {%0,%1,%2,%3}, [%4];"
                             : "=r"(bh[0]), "=r"(bh[1]), "=r"(bh[2]), "=r"(bh[3])
                             : "r"(addr));
                addr = su32(&Bl[row * ASTR + col]);
                asm volatile("ldmatrix.sync.aligned.m8n8.x4.shared.b16 {%0,%1,%2,%3}, [%4];"
                             : "=r"(bl[0]), "=r"(bl[1]), "=r"(bl[2]), "=r"(bl[3])
                             : "r"(addr));
#pragma unroll
                for (int i = 0; i < 2; i++) {
#pragma unroll
                    for (int jj = 0; jj < 2; jj++) {
                        int j = j2 * 2 + jj;
                        unsigned b0h = bh[jj ? 2 : 0], b1h = bh[jj ? 3 : 1];
                        unsigned b0l = bl[jj ? 2 : 0], b1l = bl[jj ? 3 : 1];
                        asm volatile(
                            "mma.sync.aligned.m16n8k16.row.col.f32.bf16.bf16.f32 "
                            "{%0,%1,%2,%3}, {%4,%5,%6,%7}, {%8,%9}, {%0,%1,%2,%3};"
                            : "+f"(acc[i][j][0]), "+f"(acc[i][j][1]),
                              "+f"(acc[i][j][2]), "+f"(acc[i][j][3])
                            : "r"(ah[i][0]), "r"(ah[i][1]), "r"(ah[i][2]), "r"(ah[i][3]),
                              "r"(b0h), "r"(b1h));
                        asm volatile(
                            "mma.sync.aligned.m16n8k16.row.col.f32.bf16.bf16.f32 "
                            "{%0,%1,%2,%3}, {%4,%5,%6,%7}, {%8,%9}, {%0,%1,%2,%3};"
                            : "+f"(acc[i][j][0]), "+f"(acc[i][j][1]),
                              "+f"(acc[i][j][2]), "+f"(acc[i][j][3])
                            : "r"(al[i][0]), "r"(al[i][1]), "r"(al[i][2]), "r"(al[i][3]),
                              "r"(b0h), "r"(b1h));
                        asm volatile(
                            "mma.sync.aligned.m16n8k16.row.col.f32.bf16.bf16.f32 "
                            "{%0,%1,%2,%3}, {%4,%5,%6,%7}, {%8,%9}, {%0,%1,%2,%3};"
                            : "+f"(acc[i][j][0]), "+f"(acc[i][j][1]),
                              "+f"(acc[i][j][2]), "+f"(acc[i][j][3])
                            : "r"(ah[i][0]), "r"(ah[i][1]), "r"(ah[i][2]), "r"(ah[i][3]),
                              "r"(b0l), "r"(b1l));
                    }
                }
            }
        }

        if (more) stage_chunk(cur ^ 1);  // STS to alt buffer overlaps nothing in-flight reads
        __syncthreads();                 // makes alt buffer visible; protects cur for reuse
        cur ^= 1;
    }

    // epilogue: bias + relu store, plus fused score partial dot
#pragma unroll
    for (int i = 0; i < 2; i++) {
        int m0 = mBase + warp_m * 32 + i * 16 + (lane >> 2);
        float rs0 = 0.f, rs1 = 0.f;    // row m0, row m0+8
#pragma unroll
        for (int j = 0; j < 4; j++) {
            int n0 = nBase + warp_n * 32 + j * 8 + ((lane & 3) << 1);
            if (n0 < Nout) {
                float bb = bias[n0], pv = pw[n0];
                float v0 = fmaxf(acc[i][j][0] + bb, 0.f);
                float v2 = fmaxf(acc[i][j][2] + bb, 0.f);
                if (m0 < M)     C[(size_t)m0 * Nout + n0]       = v0;
                if (m0 + 8 < M) C[(size_t)(m0 + 8) * Nout + n0] = v2;
                rs0 += v0 * pv; rs1 += v2 * pv;
            }
            if (n0 + 1 < Nout) {
                float bb = bias[n0 + 1], pv = pw[n0 + 1];
                float v1 = fmaxf(acc[i][j][1] + bb, 0.f);
                float v3 = fmaxf(acc[i][j][3] + bb, 0.f);
                if (m0 < M)     C[(size_t)m0 * Nout + n0 + 1]       = v1;
                if (m0 + 8 < M) C[(size_t)(m0 + 8) * Nout + n0 + 1] = v3;
                rs0 += v1 * pv; rs1 += v3 * pv;
            }
        }
        rs0 += __shfl_xor_sync(0xFFFFFFFFu, rs0, 1);
        rs0 += __shfl_xor_sync(0xFFFFFFFFu, rs0, 2);
        rs1 += __shfl_xor_sync(0xFFFFFFFFu, rs1, 1);
        rs1 += __shfl_xor_sync(0xFFFFFFFFu, rs1, 2);
        if ((lane & 3) == 0) {
            if (m0 < M)     atomicAdd(&scoreraw[m0], rs0);
            if (m0 + 8 < M) atomicAdd(&scoreraw[m0 + 8], rs1);
        }
    }
}

// ---------------- deterministic top-k selection (single block) ----------------
__device__ __forceinline__ int warpInclScan(int v) {
    int lane = threadIdx.x & 31;
#pragma unroll
    for (int o = 1; o < 32; o <<= 1) {
        int t = __shfl_up_sync(0xFFFFFFFFu, v, o);
        if (lane >= o) v += t;
    }
    return v;
}

__device__ __forceinline__ float key_to_val(unsigned u) {
    unsigned b = (u & 0x80000000u) ? (u ^ 0x80000000u) : ~u;
    return __uint_as_float(b);
}

__global__ void __launch_bounds__(1024) k_select_topk(
    const float* __restrict__ rawscore, const float* __restrict__ pw,
    int n, int k,
    int* __restrict__ sel_old, float* __restrict__ sel_val,
    int* __restrict__ new_idx, int* __restrict__ mask) {
    __shared__ unsigned skey[10016];
    __shared__ int hist[256];
    __shared__ int wsum[32];
    __shared__ int gtot[8];
    __shared__ unsigned sh_prefix;
    __shared__ int sh_rem;
    __shared__ float s_red[32];
    __shared__ float s_inv_sh;
    int tid = threadIdx.x;
    int lane = tid & 31, wid = tid >> 5;
    int iters = (n + 1023) >> 10;   // uniform trip count for all threads

    {
        float s = 0.f;
        for (int i = tid; i < HID; i += 1024) s += pw[i] * pw[i];
        for (int o = 16; o; o >>= 1) s += __shfl_down_sync(0xFFFFFFFFu, s, o);
        if (lane == 0) s_red[wid] = s;
        __syncthreads();
        if (tid == 0) {
            float t = 0.f;
            for (int i = 0; i < 32; i++) t += s_red[i];
            s_inv_sh = rsqrtf(t);
        }
        __syncthreads();
    }
    float s_inv = s_inv_sh;

    for (int i = tid; i < n; i += 1024) {
        float v = tanhf(rawscore[i] * s_inv);
        unsigned b = __float_as_uint(v);
        skey[i] = (b & 0x80000000u) ? ~b : (b | 0x80000000u);
    }
    if (tid == 0) { sh_prefix = 0u; sh_rem = k; }
    __syncthreads();

    for (int shift = 24; shift >= 0; shift -= 8) {
        if (tid < 256) hist[tid] = 0;
        __syncthreads();
        unsigned premask = (shift == 24) ? 0u : (0xFFFFFFFFu << (shift + 8));
        unsigned pre = sh_prefix;
        int rem = sh_rem;
        for (int it = 0; it < iters; it++) {
            int i = tid + (it << 10);
            bool inb = (i < n);
            unsigned u = inb ? skey[i] : 0u;
            bool p = inb && ((u & premask) == pre);
            unsigned act = __ballot_sync(0xFFFFFFFFu, p);
            if (p) {
                unsigned bin = (u >> shift) & 255u;
                unsigned peers = __match_any_sync(act, bin);
                int leader = __ffs((int)peers) - 1;
                if (lane == leader) atomicAdd(&hist[bin], __popc(peers));
            }
        }
        __syncthreads();
        {
            bool valid = (tid < 256);
            int v = valid ? hist[tid] : 0;
            int sv = v;
#pragma unroll
            for (int o = 1; o < 32; o <<= 1) {
                int t = __shfl_down_sync(0xFFFFFFFFu, sv, o);
                if (lane + o < 32) sv += t;
            }
            if (valid && lane == 0) gtot[tid >> 5] = sv;
            __syncthreads();
            if (tid == 0) {
                int acc = 0;
                for (int g = 7; g >= 0; g--) { int t = gtot[g]; gtot[g] = acc; acc += t; }
            }
            __syncthreads();
            if (valid) {
                int suf_excl = (sv - v) + gtot[tid >> 5];
                if (suf_excl < rem && suf_excl + v >= rem) {
                    sh_prefix = pre | ((unsigned)tid << shift);
                    sh_rem = rem - suf_excl;
                }
            }
        }
        __syncthreads();
    }
    unsigned T = sh_prefix;
    int r = sh_rem;

    int ch = (n + 1023) / 1024;
    int beg = tid * ch; if (beg > n) beg = n;
    int end = beg + ch; if (end > n) end = n;

    int eqc = 0;
    for (int i = beg; i < end; i++) eqc += (skey[i] == T);
    int inc = warpInclScan(eqc);
    if (lane == 31) wsum[wid] = inc;
    __syncthreads();
    if (wid == 0) { int v = wsum[lane]; int wi = warpInclScan(v); wsum[lane] = wi - v; }
    __syncthreads();
    int eqbase = wsum[wid] + inc - eqc;
    __syncthreads();

    int selc = 0;
    {
        int er = eqbase;
        for (int i = beg; i < end; i++) {
            unsigned u = skey[i];
            bool eq = (u == T);
            bool sel = (u > T) || (eq && er < r);
            if (eq) er++;
            selc += sel;
        }
    }
    int inc2 = warpInclScan(selc);
    if (lane == 31) wsum[wid] = inc2;
    __syncthreads();
    if (wid == 0) { int v = wsum[lane]; int wi = warpInclScan(v); wsum[lane] = wi - v; }
    __syncthreads();
    int selbase = wsum[wid] + inc2 - selc;

    {
        int er = eqbase, pos = selbase;
        for (int i = beg; i < end; i++) {
            unsigned u = skey[i];
            bool eq = (u == T);
            bool sel = (u > T) || (eq && er < r);
            if (eq) er++;
            if (sel) {
                sel_old[pos] = i;
                sel_val[pos] = key_to_val(u);
                new_idx[i] = pos;
                mask[i] = 1;
                pos++;
            } else {
                new_idx[i] = 0;
                mask[i] = 0;
            }
        }
    }
}

// ---------------- gather pooled features + fused max/sum readout ----------------
__global__ void k_gather_pool(const float* __restrict__ h, int kcnt,
                              const int* __restrict__ sel_old, const float* __restrict__ sel_val,
                              float* __restrict__ hp, unsigned* __restrict__ maxb,
                              float* __restrict__ sumb) {
    int c = blockIdx.x * blockDim.x + threadIdx.x;
    if (c >= HID) return;
    int rpb = (kcnt + gridDim.y - 1) / gridDim.y;
    int r0 = blockIdx.y * rpb;
    int r1 = r0 + rpb; if (r1 > kcnt) r1 = kcnt;
    unsigned mk = 0u;
    float sm = 0.f;
    for (int p = r0; p < r1; p++) {
        int old = sel_old[p];
        float v = h[(size_t)old * HID + c] * sel_val[p];
        if (hp) hp[(size_t)p * HID + c] = v;
        unsigned b = __float_as_uint(v);
        unsigned kk = (b & 0x80000000u) ? ~b : (b | 0x80000000u);
        if (kk > mk) mk = kk;
        sm += v;
    }
    if (r1 > r0) { atomicMax(&maxb[c], mk); atomicAdd(&sumb[c], sm); }
}

__global__ void k_finalize_readout(const unsigned* __restrict__ maxb,
                                   const float* __restrict__ sumb,
                                   float* __restrict__ xo, float invk) {
    int c = blockIdx.x * blockDim.x + threadIdx.x;
    if (c < HID) {
        unsigned u = maxb[c];
        unsigned b = (u & 0x80000000u) ? (u ^ 0x80000000u) : ~u;
        xo[c] = __uint_as_float(b);
        xo[HID + c] = sumb[c] * invk;
    }
}

__global__ void k_add_z() {
    int i = blockIdx.x * blockDim.x + threadIdx.x;
    if (i < 1000) g_z[i] = g_x1[i] + g_x2[i];
}

// ---------------- GEMV: y = act(W @ x + b), warp per row ----------------
__global__ void k_gemv_act(const float* __restrict__ W, const float* __restrict__ b,
                           const float* __restrict__ x, float* __restrict__ y,
                           int R, int K, int act) {
    int w = (blockIdx.x * blockDim.x + threadIdx.x) >> 5;
    int lane = threadIdx.x & 31;
    if (w >= R) return;
    const float4* W4 = (const float4*)(W + (size_t)w * K);
    const float4* X4 = (const float4*)x;
    int K4 = K >> 2;
    float s = 0.f;
    for (int i = lane; i < K4; i += 32) {
        float4 a = W4[i], c = X4[i];
        s += a.x * c.x + a.y * c.y + a.z * c.z + a.w * c.w;
    }
    for (int o = 16; o; o >>= 1) s += __shfl_down_sync(0xFFFFFFFFu, s, o);
    if (lane == 0) {
        s += b[w];
        y[w] = (act == 0) ? fmaxf(s, 0.f) : 1.f / (1.f + expf(-s));
    }
}

// ---------------- launch ----------------
extern "C" void kernel_launch(void* const* d_in, const int* in_sizes, int n_in,
                              void* d_out, int out_size) {
    const float* x       = (const float*)d_in[0];
    const int*   esrc    = (const int*)d_in[1];
    const int*   edst    = (const int*)d_in[2];
    const float* ew      = (const float*)d_in[3];
    const float* W1_rel  = (const float*)d_in[4];
    const float* b1      = (const float*)d_in[5];
    const float* W1_root = (const float*)d_in[6];
    const float* p1      = (const float*)d_in[7];
    const float* W2_rel  = (const float*)d_in[8];
    const float* b2      = (const float*)d_in[9];
    const float* W2_root = (const float*)d_in[10];
    const float* p2      = (const float*)d_in[11];
    const float* l1W     = (const float*)d_in[12];
    const float* l1b     = (const float*)d_in[13];
    const float* l2W     = (const float*)d_in[14];
    const float* l2b     = (const float*)d_in[15];
    const float* l3W     = (const float*)d_in[16];
    const float* l3b     = (const float*)d_in[17];
    float* out = (float*)d_out;

    float *p_agg1, *p_h1, *p_hp1, *p_agg2, *p_h2, *p_sc1, *p_sc2, *p_selval;
    float *p_x1, *p_x2, *p_z, *p_t1, *p_t2, *p_sum1, *p_sum2;
    int *p_selold, *p_newidx, *p_mask;
    unsigned *p_max1, *p_max2;
    cudaGetSymbolAddress((void**)&p_agg1, g_agg1);
    cudaGetSymbolAddress((void**)&p_h1, g_h1);
    cudaGetSymbolAddress((void**)&p_hp1, g_hp1);
    cudaGetSymbolAddress((void**)&p_agg2, g_agg2);
    cudaGetSymbolAddress((void**)&p_h2, g_h2);
    cudaGetSymbolAddress((void**)&p_sc1, g_score1);
    cudaGetSymbolAddress((void**)&p_sc2, g_score2);
    cudaGetSymbolAddress((void**)&p_selval, g_selval);
    cudaGetSymbolAddress((void**)&p_selold, g_selold);
    cudaGetSymbolAddress((void**)&p_newidx, g_newidx);
    cudaGetSymbolAddress((void**)&p_mask, g_mask);
    cudaGetSymbolAddress((void**)&p_max1, g_max1);
    cudaGetSymbolAddress((void**)&p_sum1, g_sum1);
    cudaGetSymbolAddress((void**)&p_max2, g_max2);
    cudaGetSymbolAddress((void**)&p_sum2, g_sum2);
    cudaGetSymbolAddress((void**)&p_x1, g_x1);
    cudaGetSymbolAddress((void**)&p_x2, g_x2);
    cudaGetSymbolAddress((void**)&p_z, g_z);
    cudaGetSymbolAddress((void**)&p_t1, g_t1);
    cudaGetSymbolAddress((void**)&p_t2, g_t2);

    static int smem_set = 0;
    if (!smem_set) {
        cudaFuncSetAttribute(k_gemm_fused_relu,
                             cudaFuncAttributeMaxDynamicSharedMemorySize, SMEM_BYTES);
        smem_set = 1;
    }

    k_zero_init<<<4096, 256>>>();

    // ---- conv1 (+score1 fused) ----
    k_scatter1<<<(int)(((long long)EDG * 64 + 255) / 256), 256>>>(x, esrc, edst, ew);
    {
        dim3 g(NPAD / BN, (N1 + BM - 1) / BM);
        k_gemm_fused_relu<<<g, 256, SMEM_BYTES>>>(p_agg1, W1_rel, x, W1_root, FIN, FIN,
                                                  b1, p1, p_h1, p_sc1, N1, HID, HID);
    }

    // ---- pool1 + readout1 ----
    k_select_topk<<<1, 1024>>>(p_sc1, p1, N1, K1SEL, p_selold, p_selval, p_newidx, p_mask);
    {
        dim3 g(4, 32);
        k_gather_pool<<<g, 128>>>(p_h1, K1SEL, p_selold, p_selval, p_hp1, p_max1, p_sum1);
    }
    k_finalize_readout<<<4, 128>>>(p_max1, p_sum1, p_x1, 1.f / (float)K1SEL);

    // ---- conv2 (+score2 fused) ----
    k_compact<<<(EDG + 255) / 256, 256>>>(esrc, edst, ew);
    k_scatter2c<<<(int)(((long long)EDG * 125 + 511) / 512), 512>>>();
    {
        dim3 g(NPAD / BN, (K1SEL + BM - 1) / BM);
        k_gemm_fused_relu<<<g, 256, SMEM_BYTES>>>(p_agg2, W2_rel, p_hp1, W2_root, HID, 512,
                                                  b2, p2, p_h2, p_sc2, K1SEL, HID, HID);
    }

    // ---- pool2 + readout2 ----
    k_select_topk<<<1, 1024>>>(p_sc2, p2, K1SEL, K2SEL, p_selold, p_selval, p_newidx, p_mask);
    {
        dim3 g(4, 32);
        k_gather_pool<<<g, 128>>>(p_h2, K2SEL, p_selold, p_selval, nullptr, p_max2, p_sum2);
    }
    k_finalize_readout<<<4, 128>>>(p_max2, p_sum2, p_x2, 1.f / (float)K2SEL);

    // ---- MLP head ----
    k_add_z<<<1, 1024>>>();
    k_gemv_act<<<(2000 + 7) / 8, 256>>>(l1W, l1b, p_z, p_t1, 2000, 1000, 0);
    k_gemv_act<<<(4000 + 7) / 8, 256>>>(l2W, l2b, p_t1, p_t2, 4000, 2000, 0);
    k_gemv_act<<<(100 + 7) / 8, 256>>>(l3W, l3b, p_t2, out, 100, 4000, 1);
}